// round 11
// baseline (speedup 1.0000x reference)
#include <cuda_runtime.h>
#include <cuda_bf16.h>
#include <cuda_fp16.h>
#include <math_constants.h>
#include <cstdint>

#define B_  2
#define N_  2048
#define E_  1024
#define H_  16
#define D_  64
#define M_  (B_ * N_)
#define K3_ 3072

// ---------------- scratch ----------------
__device__ __half g_Qs[M_ * 2048];            // fp16 [row][head][64hi|64lo]
__device__ __half g_Ks[M_ * 2048];
__device__ __half g_Vs[M_ * 2048];
__device__ __nv_bfloat16 g_xext[M_ * K3_];    // [hi|lo|hi]
__device__ __nv_bfloat16 g_cext[M_ * K3_];    // [hi|lo|hi], written by flash
__device__ __nv_bfloat16 g_wqext[E_ * K3_];   // [hi|hi|lo]
__device__ __nv_bfloat16 g_wkext[E_ * K3_];
__device__ __nv_bfloat16 g_wvext[E_ * K3_];
__device__ __nv_bfloat16 g_woext[E_ * K3_];

// ---------------- helpers ----------------
__device__ __forceinline__ uint32_t smem_u32(const void* p) {
    uint32_t a;
    asm("{ .reg .u64 t; cvta.to.shared.u64 t, %1; cvt.u32.u64 %0, t; }" : "=r"(a) : "l"(p));
    return a;
}
// bf16 mma (projection GEMMs)
__device__ __forceinline__ void mma16816(float* c, const uint32_t* a, const uint32_t* b) {
    asm volatile(
        "mma.sync.aligned.m16n8k16.row.col.f32.bf16.bf16.f32 "
        "{%0,%1,%2,%3}, {%4,%5,%6,%7}, {%8,%9}, {%0,%1,%2,%3};"
        : "+f"(c[0]), "+f"(c[1]), "+f"(c[2]), "+f"(c[3])
        : "r"(a[0]), "r"(a[1]), "r"(a[2]), "r"(a[3]), "r"(b[0]), "r"(b[1]));
}
// fp16 mma (attention)
__device__ __forceinline__ void mma16816f(float* c, const uint32_t* a, const uint32_t* b) {
    asm volatile(
        "mma.sync.aligned.m16n8k16.row.col.f32.f16.f16.f32 "
        "{%0,%1,%2,%3}, {%4,%5,%6,%7}, {%8,%9}, {%0,%1,%2,%3};"
        : "+f"(c[0]), "+f"(c[1]), "+f"(c[2]), "+f"(c[3])
        : "r"(a[0]), "r"(a[1]), "r"(a[2]), "r"(a[3]), "r"(b[0]), "r"(b[1]));
}
__device__ __forceinline__ void ldsm4(uint32_t* r, uint32_t addr) {
    asm volatile("ldmatrix.sync.aligned.m8n8.x4.shared.b16 {%0,%1,%2,%3}, [%4];"
        : "=r"(r[0]), "=r"(r[1]), "=r"(r[2]), "=r"(r[3]) : "r"(addr));
}
__device__ __forceinline__ void ldsm4t(uint32_t* r, uint32_t addr) {
    asm volatile("ldmatrix.sync.aligned.m8n8.x4.trans.shared.b16 {%0,%1,%2,%3}, [%4];"
        : "=r"(r[0]), "=r"(r[1]), "=r"(r[2]), "=r"(r[3]) : "r"(addr));
}
__device__ __forceinline__ void cp_async16(uint32_t s, const void* g) {
    asm volatile("cp.async.cg.shared.global [%0], [%1], 16;" :: "r"(s), "l"(g) : "memory");
}
__device__ __forceinline__ void cp_commit() {
    asm volatile("cp.async.commit_group;" ::: "memory");
}
__device__ __forceinline__ void pack_hl(float x, float y, uint32_t& hi, uint32_t& lo) {
    __nv_bfloat162 h2 = __floats2bfloat162_rn(x, y);
    float rx = x - __bfloat162float(h2.x);
    float ry = y - __bfloat162float(h2.y);
    __nv_bfloat162 l2 = __floats2bfloat162_rn(rx, ry);
    hi = *reinterpret_cast<uint32_t*>(&h2);
    lo = *reinterpret_cast<uint32_t*>(&l2);
}
__device__ __forceinline__ void pack_hl_f16(float x, float y, uint32_t& hi, uint32_t& lo) {
    __half2 h2 = __floats2half2_rn(x, y);
    float rx = x - __half2float(__low2half(h2));
    float ry = y - __half2float(__high2half(h2));
    __half2 l2 = __floats2half2_rn(rx, ry);
    hi = *reinterpret_cast<uint32_t*>(&h2);
    lo = *reinterpret_cast<uint32_t*>(&l2);
}

// ---------------- x conversion: [hi|lo|hi] bf16 ----------------
__global__ __launch_bounds__(256) void cvt_x(
    const float* __restrict__ in, __nv_bfloat16* __restrict__ out)
{
    int idx = blockIdx.x * 256 + threadIdx.x;
    int r = idx >> 8;
    int c = (idx & 255) << 2;
    float4 v = *reinterpret_cast<const float4*>(in + (size_t)r * E_ + c);
    uint32_t h0, l0, h1, l1;
    pack_hl(v.x, v.y, h0, l0);
    pack_hl(v.z, v.w, h1, l1);
    uint32_t* o = reinterpret_cast<uint32_t*>(out + (size_t)r * K3_);
    int cw = c >> 1;
    o[cw] = h0; o[cw + 1] = h1;
    o[512 + cw] = l0; o[512 + cw + 1] = l1;
    o[1024 + cw] = h0; o[1024 + cw + 1] = h1;
}

// ---------------- weight conversion (4 fused): [hi|hi|lo] bf16 ----------------
__global__ __launch_bounds__(256) void cvt_w4(
    const float* __restrict__ W0, const float* __restrict__ W1,
    const float* __restrict__ W2, const float* __restrict__ W3,
    __nv_bfloat16* __restrict__ O0, __nv_bfloat16* __restrict__ O1,
    __nv_bfloat16* __restrict__ O2, __nv_bfloat16* __restrict__ O3)
{
    int sel = blockIdx.y;
    const float* in = sel == 0 ? W0 : sel == 1 ? W1 : sel == 2 ? W2 : W3;
    __nv_bfloat16* out = sel == 0 ? O0 : sel == 1 ? O1 : sel == 2 ? O2 : O3;
    int idx = blockIdx.x * 256 + threadIdx.x;
    int r = idx >> 8;
    int c = (idx & 255) << 2;
    float4 v = *reinterpret_cast<const float4*>(in + (size_t)r * E_ + c);
    uint32_t h0, l0, h1, l1;
    pack_hl(v.x, v.y, h0, l0);
    pack_hl(v.z, v.w, h1, l1);
    uint32_t* o = reinterpret_cast<uint32_t*>(out + (size_t)r * K3_);
    int cw = c >> 1;
    o[cw] = h0; o[cw + 1] = h1;
    o[512 + cw] = h0;  o[512 + cw + 1] = h1;
    o[1024 + cw] = l0; o[1024 + cw + 1] = l1;
}

// ---------------- HMMA NT GEMM (bf16, ldmatrix), 4-stage, 2 CTAs/SM ----------------
#define GS_W 20
#define G_STAGE_W (256 * GS_W)
#define G_SMEM_BYTES (4 * G_STAGE_W * 4)

template<int SPLIT>
__global__ __launch_bounds__(256, 2) void gemm_mma_t(
    const __nv_bfloat16* __restrict__ A,
    const __nv_bfloat16* __restrict__ W0, const __nv_bfloat16* __restrict__ W1,
    const __nv_bfloat16* __restrict__ W2,
    const float* __restrict__ b0, const float* __restrict__ b1, const float* __restrict__ b2,
    float* __restrict__ Cf,
    __half* __restrict__ S0, __half* __restrict__ S1, __half* __restrict__ S2)
{
    extern __shared__ uint32_t smw[];
    const int z = blockIdx.z;
    const __nv_bfloat16* W = (z == 0) ? W0 : (z == 1) ? W1 : W2;
    const float* bias = (z == 0) ? b0 : (z == 1) ? b1 : b2;
    __half* Sp = (z == 0) ? S0 : (z == 1) ? S1 : S2;

    const int tid = threadIdx.x;
    const int wid = tid >> 5, lane = tid & 31;
    const int g = lane >> 2, t4 = lane & 3;
    const int wm = wid & 3, wn = wid >> 2;
    const int m0 = blockIdx.y * 128;
    const int n0 = blockIdx.x * 128;
    const int NT = K3_ / 32;
    const uint32_t smb = smem_u32(smw);

    auto issue = [&](int kt) {
        const int sb = (kt & 3) * G_STAGE_W;
#pragma unroll
        for (int u = 0; u < 2; u++) {
            int c = tid + 256 * u;
            int row = c >> 2, k4 = c & 3;
            uint32_t sa = smb + (sb + row * GS_W + k4 * 4) * 4;
            cp_async16(sa, A + (size_t)(m0 + row) * K3_ + kt * 32 + k4 * 8);
            cp_async16(sa + 128 * GS_W * 4, W + (size_t)(n0 + row) * K3_ + kt * 32 + k4 * 8);
        }
        cp_commit();
    };

    float acc[2][8][4];
#pragma unroll
    for (int i = 0; i < 2; i++)
#pragma unroll
        for (int j = 0; j < 8; j++)
#pragma unroll
            for (int q = 0; q < 4; q++) acc[i][j][q] = 0.0f;

    issue(0); issue(1); issue(2);

    const int a_row = 32 * wm + (lane & 15);
    const int a_cw  = 4 * (lane >> 4);
    const int b_row = 64 * wn + (lane & 7) + 8 * (lane >> 4);
    const int b_cw  = 4 * ((lane >> 3) & 1);

    for (int kt = 0; kt < NT; kt++) {
        if (kt < NT - 2)       asm volatile("cp.async.wait_group 2;" ::: "memory");
        else if (kt == NT - 2) asm volatile("cp.async.wait_group 1;" ::: "memory");
        else                   asm volatile("cp.async.wait_group 0;" ::: "memory");
        __syncthreads();
        if (kt + 3 < NT) issue(kt + 3);

        const int sb = (kt & 3) * G_STAGE_W;
        const int bb = sb + 128 * GS_W;
#pragma unroll
        for (int kk = 0; kk < 2; kk++) {
            uint32_t a[2][4], b[8][2];
#pragma unroll
            for (int i = 0; i < 2; i++)
                ldsm4(a[i], smb + (sb + (a_row + 16 * i) * GS_W + a_cw + 8 * kk) * 4);
#pragma unroll
            for (int jp = 0; jp < 4; jp++) {
                uint32_t r4[4];
                ldsm4(r4, smb + (bb + (b_row + 16 * jp) * GS_W + b_cw + 8 * kk) * 4);
                b[2 * jp][0] = r4[0]; b[2 * jp][1] = r4[1];
                b[2 * jp + 1][0] = r4[2]; b[2 * jp + 1][1] = r4[3];
            }
#pragma unroll
            for (int i = 0; i < 2; i++)
#pragma unroll
                for (int j = 0; j < 8; j++) mma16816(acc[i][j], a[i], b[j]);
        }
    }

    if (SPLIT) {
        const int head = (n0 + 64 * wn) >> 6;
        uint32_t* outw = reinterpret_cast<uint32_t*>(Sp);
#pragma unroll
        for (int i = 0; i < 2; i++) {
            int row = m0 + 32 * wm + 16 * i + g;
#pragma unroll
            for (int j = 0; j < 8; j++) {
                int d = 8 * j + 2 * t4;
                float2 bb2 = *reinterpret_cast<const float2*>(bias + n0 + 64 * wn + d);
                uint32_t hi, lo;
                int w0 = row * 1024 + head * 64 + (d >> 1);
                pack_hl_f16(acc[i][j][0] + bb2.x, acc[i][j][1] + bb2.y, hi, lo);
                outw[w0] = hi; outw[w0 + 32] = lo;
                w0 += 8 * 1024;
                pack_hl_f16(acc[i][j][2] + bb2.x, acc[i][j][3] + bb2.y, hi, lo);
                outw[w0] = hi; outw[w0 + 32] = lo;
            }
        }
    } else {
#pragma unroll
        for (int i = 0; i < 2; i++) {
            int row = m0 + 32 * wm + 16 * i + g;
#pragma unroll
            for (int j = 0; j < 8; j++) {
                int col = n0 + 64 * wn + 8 * j + 2 * t4;
                float2 bb2 = *reinterpret_cast<const float2*>(bias + col);
                float2 v0 = { acc[i][j][0] + bb2.x, acc[i][j][1] + bb2.y };
                float2 v1 = { acc[i][j][2] + bb2.x, acc[i][j][3] + bb2.y };
                *reinterpret_cast<float2*>(Cf + (size_t)row * E_ + col) = v0;
                *reinterpret_cast<float2*>(Cf + (size_t)(row + 8) * E_ + col) = v1;
            }
        }
    }
}

// ---------------- Flash attention: fp16 2-term, 128 threads, 4 warps x m32 ----------------
// QT=128, KT=64. smem words:
//   Q: [0, 8704)  rows 0..127, stride 68: [hi 32w | lo 32w | pad 4w]
//   K: 2 bufs @ 8704, each 64 x 36 (hi only)
//   V: 2 bufs @ 13312, each 64 x 36 (hi only)
#define FQT 128
#define FKT 64
#define QS_W 68
#define KS_W 36
#define VS_W 36
#define KB0 8704
#define KBUF_W (64 * KS_W)            // 2304
#define VB0 (KB0 + 2 * KBUF_W)        // 13312
#define VBUF_W (64 * VS_W)            // 2304
#define F_SMEM_BYTES ((VB0 + 2 * VBUF_W) * 4)   // 71680

__global__ __launch_bounds__(128, 2) void flash_mma(
    const __half* __restrict__ Qg, const __half* __restrict__ Kg,
    const __half* __restrict__ Vg, uint32_t* __restrict__ Cw)
{
    extern __shared__ uint32_t smw[];
    const uint32_t smb = smem_u32(smw);
    const int tid = threadIdx.x;
    const int wid = tid >> 5, lane = tid & 31;
    const int g = lane >> 2, t4 = lane & 3;
    const int bz = blockIdx.z, hh = blockIdx.y;
    const int q0 = blockIdx.x * FQT;

    // ---- issue Q (hi+lo, one group): 2048 chunks / 128 thr ----
    {
        const char* qg = (const char*)Qg + ((size_t)(bz * N_ + q0) * 2048 + hh * 128) * 2;
#pragma unroll
        for (int u = 0; u < 16; u++) {
            int c = tid + 128 * u;
            int row = c >> 4, p = c & 15;
            cp_async16(smb + (row * QS_W + p * 4) * 4, qg + (size_t)row * 4096 + p * 16);
        }
        cp_commit();
    }
    // ---- issue K/V hi-only: 512 chunks each ----
    auto issue_kv = [&](int t) {
        const int b = t & 1;
        const char* kg = (const char*)Kg + ((size_t)(bz * N_ + t * 64) * 2048 + hh * 128) * 2;
        const char* vg = (const char*)Vg + ((size_t)(bz * N_ + t * 64) * 2048 + hh * 128) * 2;
#pragma unroll
        for (int u = 0; u < 4; u++) {
            int c = tid + 128 * u;
            int row = c >> 3, p = c & 7;
            cp_async16(smb + ((KB0 + b * KBUF_W) + row * KS_W + p * 4) * 4,
                       kg + (size_t)row * 4096 + p * 16);
        }
#pragma unroll
        for (int u = 0; u < 4; u++) {
            int c = tid + 128 * u;
            int row = c >> 3, p = c & 7;
            cp_async16(smb + ((VB0 + b * VBUF_W) + row * VS_W + p * 4) * 4,
                       vg + (size_t)row * 4096 + p * 16);
        }
        cp_commit();
    };

    issue_kv(0);
    asm volatile("cp.async.wait_group 1;" ::: "memory");   // Q resident
    __syncthreads();

    // ---- hoist Q-hi fragments ----
    const int qa_row = 32 * wid + (lane & 15);
    const int qa_cw  = 4 * (lane >> 4);
    uint32_t qh[2][4][4];
#pragma unroll
    for (int i = 0; i < 2; i++)
#pragma unroll
        for (int kc = 0; kc < 4; kc++)
            ldsm4(qh[i][kc], smb + ((qa_row + 16 * i) * QS_W + qa_cw + 8 * kc) * 4);

    float o[2][8][4], mrow[2][2], lrow[2][2];
#pragma unroll
    for (int i = 0; i < 2; i++) {
        mrow[i][0] = mrow[i][1] = -CUDART_INF_F;
        lrow[i][0] = lrow[i][1] = 0.0f;
#pragma unroll
        for (int j = 0; j < 8; j++)
#pragma unroll
            for (int q = 0; q < 4; q++) o[i][j][q] = 0.0f;
    }

    const int kb_row = (lane & 7) + 8 * (lane >> 4);
    const int kb_cw  = 4 * ((lane >> 3) & 1);
    const int tsel = lane >> 3;

    for (int t = 0; t < N_ / FKT; t++) {
        if (t + 1 < N_ / FKT) {
            issue_kv(t + 1);
            asm volatile("cp.async.wait_group 1;" ::: "memory");
        } else {
            asm volatile("cp.async.wait_group 0;" ::: "memory");
        }
        __syncthreads();
        const int koff = KB0 + (t & 1) * KBUF_W;
        const int voff = VB0 + (t & 1) * VBUF_W;

        // ---- S = (Qh + Ql) Kh : 2 passes per kc ----
        float s[2][8][4];
#pragma unroll
        for (int i = 0; i < 2; i++)
#pragma unroll
            for (int j = 0; j < 8; j++)
#pragma unroll
                for (int q = 0; q < 4; q++) s[i][j][q] = 0.0f;

#pragma unroll
        for (int kc = 0; kc < 4; kc++) {
            uint32_t kb[8][2];
#pragma unroll
            for (int jp = 0; jp < 4; jp++) {
                uint32_t r4[4];
                ldsm4(r4, smb + (koff + (kb_row + 16 * jp) * KS_W + kb_cw + 8 * kc) * 4);
                kb[2 * jp][0] = r4[0]; kb[2 * jp][1] = r4[1];
                kb[2 * jp + 1][0] = r4[2]; kb[2 * jp + 1][1] = r4[3];
            }
#pragma unroll
            for (int i = 0; i < 2; i++)
#pragma unroll
                for (int j = 0; j < 8; j++) mma16816f(s[i][j], qh[i][kc], kb[j]);
            uint32_t ql[2][4];
#pragma unroll
            for (int i = 0; i < 2; i++)
                ldsm4(ql[i], smb + ((qa_row + 16 * i) * QS_W + 32 + qa_cw + 8 * kc) * 4);
#pragma unroll
            for (int i = 0; i < 2; i++)
#pragma unroll
                for (int j = 0; j < 8; j++) mma16816f(s[i][j], ql[i], kb[j]);
        }

        // ---- online softmax ----
#pragma unroll
        for (int i = 0; i < 2; i++) {
#pragma unroll
            for (int h = 0; h < 2; h++) {
                float mx = -CUDART_INF_F;
#pragma unroll
                for (int j = 0; j < 8; j++)
                    mx = fmaxf(mx, fmaxf(s[i][j][2 * h], s[i][j][2 * h + 1]));
                mx = fmaxf(mx, __shfl_xor_sync(0xFFFFFFFFu, mx, 1));
                mx = fmaxf(mx, __shfl_xor_sync(0xFFFFFFFFu, mx, 2));
                float mnew = fmaxf(mrow[i][h], mx);
                float alpha = __expf(mrow[i][h] - mnew);
                mrow[i][h] = mnew;
                float ls = 0.0f;
#pragma unroll
                for (int j = 0; j < 8; j++) {
                    float p0 = __expf(s[i][j][2 * h] - mnew);
                    float p1 = __expf(s[i][j][2 * h + 1] - mnew);
                    ls += p0 + p1;
                    s[i][j][2 * h] = p0; s[i][j][2 * h + 1] = p1;
                }
                ls += __shfl_xor_sync(0xFFFFFFFFu, ls, 1);
                ls += __shfl_xor_sync(0xFFFFFFFFu, ls, 2);
                lrow[i][h] = lrow[i][h] * alpha + ls;
#pragma unroll
                for (int j = 0; j < 8; j++) {
                    o[i][j][2 * h] *= alpha; o[i][j][2 * h + 1] *= alpha;
                }
            }
        }

        // ---- PV: (Ph + Pl) Vh : per-kc pack + 2 passes ----
#pragma unroll
        for (int kc = 0; kc < 4; kc++) {
            uint32_t ph[2][2], phB[2][2], pl[2][2], plB[2][2];
#pragma unroll
            for (int i = 0; i < 2; i++)
#pragma unroll
                for (int jj = 0; jj < 2; jj++) {
                    int j = 2 * kc + jj;
                    pack_hl_f16(s[i][j][0], s[i][j][1], ph[i][jj], pl[i][jj]);
                    pack_hl_f16(s[i][j][2], s[i][j][3], phB[i][jj], plB[i][jj]);
                }
            uint32_t vb[8][2];
#pragma unroll
            for (int jj = 0; jj < 8; jj += 2) {
                uint32_t r4[4];
                int row = 16 * kc + 8 * (tsel & 1) + (lane & 7);
                ldsm4t(r4, smb + (voff + row * VS_W) * 4 + 16 * (jj + (tsel >> 1)));
                vb[jj][0] = r4[0]; vb[jj][1] = r4[1];
                vb[jj + 1][0] = r4[2]; vb[jj + 1][1] = r4[3];
            }
#pragma unroll
            for (int i = 0; i < 2; i++) {
                uint32_t pa[4] = { ph[i][0], phB[i][0], ph[i][1], phB[i][1] };
#pragma unroll
                for (int j = 0; j < 8; j++) mma16816f(o[i][j], pa, vb[j]);
            }
#pragma unroll
            for (int i = 0; i < 2; i++) {
                uint32_t pa[4] = { pl[i][0], plB[i][0], pl[i][1], plB[i][1] };
#pragma unroll
                for (int j = 0; j < 8; j++) mma16816f(o[i][j], pa, vb[j]);
            }
        }
        __syncthreads();
    }

    // ---- epilogue: write bf16 split context into [hi|lo|hi] ----
#pragma unroll
    for (int i = 0; i < 2; i++) {
        float inv0 = 1.0f / (lrow[i][0] * 32.0f);
        float inv1 = 1.0f / (lrow[i][1] * 32.0f);
        int row = bz * N_ + q0 + 32 * wid + 16 * i + g;
#pragma unroll
        for (int j = 0; j < 8; j++) {
            int cw = (hh * 64 + 8 * j + 2 * t4) >> 1;
            uint32_t hi, lo;
            int base = row * 1536;
            pack_hl(o[i][j][0] * inv0, o[i][j][1] * inv0, hi, lo);
            Cw[base + cw] = hi; Cw[base + 512 + cw] = lo; Cw[base + 1024 + cw] = hi;
            base = (row + 8) * 1536;
            pack_hl(o[i][j][2] * inv1, o[i][j][3] * inv1, hi, lo);
            Cw[base + cw] = hi; Cw[base + 512 + cw] = lo; Cw[base + 1024 + cw] = hi;
        }
    }
}

// ---------------- launcher ----------------
extern "C" void kernel_launch(void* const* d_in, const int* in_sizes, int n_in,
                              void* d_out, int out_size)
{
    const float* x  = (const float*)d_in[0];
    const float* Wq = (const float*)d_in[1];
    const float* bq = (const float*)d_in[2];
    const float* Wk = (const float*)d_in[3];
    const float* bk = (const float*)d_in[4];
    const float* Wv = (const float*)d_in[5];
    const float* bv = (const float*)d_in[6];
    const float* Wo = (const float*)d_in[7];
    const float* bo = (const float*)d_in[8];
    float* out = (float*)d_out;

    cudaFuncSetAttribute(gemm_mma_t<1>, cudaFuncAttributeMaxDynamicSharedMemorySize, G_SMEM_BYTES);
    cudaFuncSetAttribute(gemm_mma_t<0>, cudaFuncAttributeMaxDynamicSharedMemorySize, G_SMEM_BYTES);
    cudaFuncSetAttribute(flash_mma, cudaFuncAttributeMaxDynamicSharedMemorySize, F_SMEM_BYTES);

    __half *Qs, *Ks, *Vs;
    __nv_bfloat16 *xe, *ce, *wqe, *wke, *wve, *woe;
    cudaGetSymbolAddress((void**)&Qs, g_Qs);
    cudaGetSymbolAddress((void**)&Ks, g_Ks);
    cudaGetSymbolAddress((void**)&Vs, g_Vs);
    cudaGetSymbolAddress((void**)&xe, g_xext);
    cudaGetSymbolAddress((void**)&ce, g_cext);
    cudaGetSymbolAddress((void**)&wqe, g_wqext);
    cudaGetSymbolAddress((void**)&wke, g_wkext);
    cudaGetSymbolAddress((void**)&wve, g_wvext);
    cudaGetSymbolAddress((void**)&woe, g_woext);

    cvt_x<<<M_, 256>>>(x, xe);
    dim3 wgrid(E_, 4);
    cvt_w4<<<wgrid, 256>>>(Wq, Wk, Wv, Wo, wqe, wke, wve, woe);

    dim3 ggrid3(E_ / 128, M_ / 128, 3);
    gemm_mma_t<1><<<ggrid3, 256, G_SMEM_BYTES>>>(
        xe, wqe, wke, wve, bq, bk, bv, nullptr, Qs, Ks, Vs);

    dim3 fgrid(N_ / FQT, H_, B_);
    flash_mma<<<fgrid, 128, F_SMEM_BYTES>>>(Qs, Ks, Vs, (uint32_t*)ce);

    dim3 ggrid1(E_ / 128, M_ / 128, 1);
    gemm_mma_t<0><<<ggrid1, 256, G_SMEM_BYTES>>>(
        ce, woe, woe, woe, bo, bo, bo, out, nullptr, nullptr, nullptr);
}